// round 1
// baseline (speedup 1.0000x reference)
#include <cuda_runtime.h>

// Problem shapes (fixed by the dataset): b=4, n1=16384, n2=4096, Cout=64, Cin(x2)=128.
#define COUT 64
#define PTS  32     // points per block in VN kernels
#define KCH  64     // k-chunk staged in smem
#define NCH  2048   // candidate chunk staged in smem for kNN

// Scratch (allocation-free contract -> __device__ globals)
__device__ float g_y2[COUT * 3 * 16384];   // y2 in [o][v][n2*b] layout
__device__ int   g_kidx[65536 * 3];
__device__ float g_kw[65536 * 3];

// ---------------------------------------------------------------------------
// VN linear + leaky-ReLU. Block = 256 threads = 8 ogroups x 32 points.
// Each thread accumulates 8 out-channels x 3 vector comps for one point.
// GATHER=false: write result to g_y2.
// GATHER=true : additionally add kNN-interpolated g_y2 features, write to out.
// ---------------------------------------------------------------------------
template <bool GATHER>
__global__ void __launch_bounds__(256, 2) vn_kernel(
    const float* __restrict__ x,    // [Cin][3][N]
    const float* __restrict__ Wf,   // [COUT][Cin]
    const float* __restrict__ Wd,   // [COUT][Cin]
    float* __restrict__ out,        // [COUT][3][N] (used when GATHER)
    int Cin, int N, int N2)
{
    __shared__ float wfs[KCH * COUT];
    __shared__ float wds[KCH * COUT];

    const int tid  = threadIdx.x;
    const int lane = tid & 31;
    const int og   = tid >> 5;             // 0..7
    const int pt   = blockIdx.x * PTS + lane;
    const bool valid = (pt < N);
    const int ptc  = valid ? pt : (N - 1);

    float pa[8][3], da[8][3];
#pragma unroll
    for (int i = 0; i < 8; i++)
#pragma unroll
        for (int v = 0; v < 3; v++) { pa[i][v] = 0.f; da[i][v] = 0.f; }

    for (int k0 = 0; k0 < Cin; k0 += KCH) {
        __syncthreads();
        const int kend = min(KCH, Cin - k0);
        // stage weights: global reads coalesced along k; smem store conflicts
        // are a one-time cost per block (~1K cycles), ignore.
        for (int i = tid; i < kend * COUT; i += 256) {
            int o  = i / kend;
            int kk = i - o * kend;
            wfs[kk * COUT + o] = Wf[o * Cin + k0 + kk];
            wds[kk * COUT + o] = Wd[o * Cin + k0 + kk];
        }
        __syncthreads();

#pragma unroll 2
        for (int kk = 0; kk < kend; kk++) {
            const int kb = (k0 + kk) * 3;
            const float xv0 = __ldg(&x[(kb + 0) * N + ptc]);
            const float xv1 = __ldg(&x[(kb + 1) * N + ptc]);
            const float xv2 = __ldg(&x[(kb + 2) * N + ptc]);
            const float4* wf4 = (const float4*)&wfs[kk * COUT + og * 8];
            const float4* wd4 = (const float4*)&wds[kk * COUT + og * 8];
            const float4 a0 = wf4[0], a1 = wf4[1];
            const float4 b0 = wd4[0], b1 = wd4[1];
            const float wfv[8] = {a0.x, a0.y, a0.z, a0.w, a1.x, a1.y, a1.z, a1.w};
            const float wdv[8] = {b0.x, b0.y, b0.z, b0.w, b1.x, b1.y, b1.z, b1.w};
#pragma unroll
            for (int i = 0; i < 8; i++) {
                pa[i][0] = fmaf(wfv[i], xv0, pa[i][0]);
                pa[i][1] = fmaf(wfv[i], xv1, pa[i][1]);
                pa[i][2] = fmaf(wfv[i], xv2, pa[i][2]);
                da[i][0] = fmaf(wdv[i], xv0, da[i][0]);
                da[i][1] = fmaf(wdv[i], xv1, da[i][1]);
                da[i][2] = fmaf(wdv[i], xv2, da[i][2]);
            }
        }
    }

    float up[8][3];
    if (GATHER) {
        const int   j0 = g_kidx[ptc * 3 + 0];
        const int   j1 = g_kidx[ptc * 3 + 1];
        const int   j2 = g_kidx[ptc * 3 + 2];
        const float w0 = g_kw[ptc * 3 + 0];
        const float w1 = g_kw[ptc * 3 + 1];
        const float w2 = g_kw[ptc * 3 + 2];
#pragma unroll
        for (int i = 0; i < 8; i++) {
            const int o = og * 8 + i;
#pragma unroll
            for (int v = 0; v < 3; v++) {
                const int base = (o * 3 + v) * N2;
                up[i][v] = w0 * __ldg(&g_y2[base + j0])
                         + w1 * __ldg(&g_y2[base + j1])
                         + w2 * __ldg(&g_y2[base + j2]);
            }
        }
    }

    if (!valid) return;

    float* dst = GATHER ? out : g_y2;
#pragma unroll
    for (int i = 0; i < 8; i++) {
        const int o = og * 8 + i;
        const float dot = pa[i][0] * da[i][0] + pa[i][1] * da[i][1] + pa[i][2] * da[i][2];
        const float d2  = da[i][0] * da[i][0] + da[i][1] * da[i][1] + da[i][2] * da[i][2];
        // mask: out = 0.2p + 0.8*(dot>=0 ? p : p - (dot/(d2+eps))*d)
        //           = p - (dot<0 ? 0.8*dot/(d2+eps) : 0) * d
        const float c = (dot >= 0.f) ? 0.f : (0.8f * dot / (d2 + 1e-6f));
#pragma unroll
        for (int v = 0; v < 3; v++) {
            float r = pa[i][v] - c * da[i][v];
            if (GATHER) r += up[i][v];
            dst[(o * 3 + v) * N + pt] = r;
        }
    }
}

// ---------------------------------------------------------------------------
// Exact k=3 NN per batch segment, brute force over staged smem chunks.
// r = |s|^2 - 2 q.s  is monotone in true d^2 (offset |q|^2 per-thread const).
// ---------------------------------------------------------------------------
__global__ void __launch_bounds__(256) knn_kernel(
    const float* __restrict__ p1,   // [b*n1][3]
    const float* __restrict__ p2,   // [b*n2][3]
    int n1, int n2)
{
    __shared__ float4 sc[NCH];
    const int bI = blockIdx.y;
    const int fi = blockIdx.x * 256 + threadIdx.x;
    const int fic = (fi < n1) ? fi : (n1 - 1);
    const int gq = bI * n1 + fic;

    const float qx = p1[gq * 3 + 0];
    const float qy = p1[gq * 3 + 1];
    const float qz = p1[gq * 3 + 2];
    const float qa = -2.f * qx, qb = -2.f * qy, qc = -2.f * qz;

    float b0 = 3.4e38f, b1 = 3.4e38f, b2 = 3.4e38f;
    int   i0 = 0, i1 = 0, i2 = 0;

    for (int c0 = 0; c0 < n2; c0 += NCH) {
        const int cnt = min(NCH, n2 - c0);
        __syncthreads();
        for (int i = threadIdx.x; i < cnt; i += 256) {
            const int gs = bI * n2 + c0 + i;
            const float sx = p2[gs * 3 + 0];
            const float sy = p2[gs * 3 + 1];
            const float sz = p2[gs * 3 + 2];
            sc[i] = make_float4(sx, sy, sz, sx * sx + sy * sy + sz * sz);
        }
        __syncthreads();

#pragma unroll 4
        for (int j = 0; j < cnt; j++) {
            const float4 s = sc[j];   // broadcast LDS.128
            const float r = fmaf(qa, s.x, fmaf(qb, s.y, fmaf(qc, s.z, s.w)));
            if (r < b2) {             // rarely taken warp-wide after warmup
                const int jj = c0 + j;
                if (r < b1) {
                    b2 = b1; i2 = i1;
                    if (r < b0) { b1 = b0; i1 = i0; b0 = r; i0 = jj; }
                    else        { b1 = r;  i1 = jj; }
                } else { b2 = r; i2 = jj; }
            }
        }
    }

    if (fi >= n1) return;

    const float q2 = qx * qx + qy * qy + qz * qz;
    const float d0 = fmaxf(b0 + q2, 0.f);
    const float d1 = fmaxf(b1 + q2, 0.f);
    const float d2 = fmaxf(b2 + q2, 0.f);
    const float w0 = 1.f / (d0 + 1e-8f);
    const float w1 = 1.f / (d1 + 1e-8f);
    const float w2 = 1.f / (d2 + 1e-8f);
    const float inv = 1.f / (w0 + w1 + w2);

    const int fo = (bI * n1 + fi) * 3;
    g_kidx[fo + 0] = bI * n2 + i0;
    g_kidx[fo + 1] = bI * n2 + i1;
    g_kidx[fo + 2] = bI * n2 + i2;
    g_kw[fo + 0] = w0 * inv;
    g_kw[fo + 1] = w1 * inv;
    g_kw[fo + 2] = w2 * inv;
}

// ---------------------------------------------------------------------------
// Inputs (metadata order): p1, x1, o1, p2, x2, o2, w1_feat, w1_dir, w2_feat, w2_dir
// ---------------------------------------------------------------------------
extern "C" void kernel_launch(void* const* d_in, const int* in_sizes, int n_in,
                              void* d_out, int out_size)
{
    const float* p1  = (const float*)d_in[0];
    const float* x1  = (const float*)d_in[1];
    const float* p2  = (const float*)d_in[3];
    const float* x2  = (const float*)d_in[4];
    const float* w1f = (const float*)d_in[6];
    const float* w1d = (const float*)d_in[7];
    const float* w2f = (const float*)d_in[8];
    const float* w2d = (const float*)d_in[9];
    float* out = (float*)d_out;

    const int b    = in_sizes[2];              // 4
    const int N1   = in_sizes[0] / 3;          // 65536
    const int N2   = in_sizes[3] / 3;          // 16384
    const int Cin1 = in_sizes[1] / (3 * N1);   // 64
    const int Cin2 = in_sizes[4] / (3 * N2);   // 128
    const int n1   = N1 / b;
    const int n2   = N2 / b;

    // K1: y2 = VN(x2)  ->  g_y2
    vn_kernel<false><<<(N2 + PTS - 1) / PTS, 256>>>(x2, w2f, w2d, nullptr, Cin2, N2, 0);

    // K2: exact k=3 NN per batch  ->  g_kidx / g_kw
    dim3 kg((n1 + 255) / 256, b);
    knn_kernel<<<kg, 256>>>(p1, p2, n1, n2);

    // K3: out = VN(x1) + interp(g_y2)
    vn_kernel<true><<<(N1 + PTS - 1) / PTS, 256>>>(x1, w1f, w1d, out, Cin1, N1, N2);
}

// round 3
// speedup vs baseline: 1.2016x; 1.2016x over previous
#include <cuda_runtime.h>

// Shapes (fixed by dataset): b=4, n1=16384, n2=4096, Cout=64, Cin(x2)=128.
#define COUT 64
#define PTS  32     // points per block in VN kernels
#define KCH  64     // k-chunk staged in smem
#define KNN_T 128   // knn block size
#define NCH  1024   // candidate chunk staged in smem for kNN

typedef unsigned long long ull;

// Scratch (allocation-free contract -> __device__ globals)
__device__ float g_y2[COUT * 3 * 16384];   // y2 in [o][v][N2] layout
__device__ int   g_kidx[65536 * 3];
__device__ float g_kw[65536 * 3];

// ---- packed f32x2 helpers (FFMA2 path, PTX-only on sm_103a) ----------------
__device__ __forceinline__ ull fma2(ull a, ull b, ull c) {
    ull d;
    asm("fma.rn.f32x2 %0, %1, %2, %3;" : "=l"(d) : "l"(a), "l"(b), "l"(c));
    return d;
}
__device__ __forceinline__ ull pack2(float x, float y) {
    ull d;
    asm("mov.b64 %0, {%1, %2};" : "=l"(d) : "f"(x), "f"(y));
    return d;
}
__device__ __forceinline__ float2 unpack2(ull v) {
    float2 r;
    asm("mov.b64 {%0, %1}, %2;" : "=f"(r.x), "=f"(r.y) : "l"(v));
    return r;
}

// ---------------------------------------------------------------------------
// VN linear + leaky-ReLU. Block = 256 threads = 8 ogroups x 32 points.
// Each thread owns 8 out-channels (4 packed pairs) x 3 vector comps.
// ---------------------------------------------------------------------------
template <bool GATHER>
__global__ void __launch_bounds__(256, 2) vn_kernel(
    const float* __restrict__ x,    // [Cin][3][N]
    const float* __restrict__ Wf,   // [COUT][Cin]
    const float* __restrict__ Wd,   // [COUT][Cin]
    float* __restrict__ out,        // [COUT][3][N] (used when GATHER)
    int Cin, int N, int N2)
{
    __shared__ __align__(16) float wfs[KCH * COUT];
    __shared__ __align__(16) float wds[KCH * COUT];

    const int tid  = threadIdx.x;
    const int lane = tid & 31;
    const int og   = tid >> 5;             // 0..7
    const int pt   = blockIdx.x * PTS + lane;
    const bool valid = (pt < N);
    const int ptc  = valid ? pt : (N - 1);

    ull pacc[4][3], dacc[4][3];            // pairs of out-channels
#pragma unroll
    for (int j = 0; j < 4; j++)
#pragma unroll
        for (int v = 0; v < 3; v++) { pacc[j][v] = 0ull; dacc[j][v] = 0ull; }

    for (int k0 = 0; k0 < Cin; k0 += KCH) {
        __syncthreads();
        const int kend = min(KCH, Cin - k0);
        for (int i = tid; i < kend * COUT; i += 256) {
            int o  = i / kend;
            int kk = i - o * kend;
            wfs[kk * COUT + o] = Wf[o * Cin + k0 + kk];
            wds[kk * COUT + o] = Wd[o * Cin + k0 + kk];
        }
        __syncthreads();

#pragma unroll 4
        for (int kk = 0; kk < kend; kk++) {
            const int kb = (k0 + kk) * 3;
            const float xv0 = __ldg(&x[(kb + 0) * N + ptc]);
            const float xv1 = __ldg(&x[(kb + 1) * N + ptc]);
            const float xv2 = __ldg(&x[(kb + 2) * N + ptc]);
            ull xp[3];
            xp[0] = pack2(xv0, xv0);
            xp[1] = pack2(xv1, xv1);
            xp[2] = pack2(xv2, xv2);
            const ulonglong2* wf2 = (const ulonglong2*)&wfs[kk * COUT + og * 8];
            const ulonglong2* wd2 = (const ulonglong2*)&wds[kk * COUT + og * 8];
            const ulonglong2 f01 = wf2[0], f23 = wf2[1];
            const ulonglong2 d01 = wd2[0], d23 = wd2[1];
            const ull fw[4] = {f01.x, f01.y, f23.x, f23.y};
            const ull dw[4] = {d01.x, d01.y, d23.x, d23.y};
#pragma unroll
            for (int j = 0; j < 4; j++) {
#pragma unroll
                for (int v = 0; v < 3; v++) {
                    pacc[j][v] = fma2(fw[j], xp[v], pacc[j][v]);
                    dacc[j][v] = fma2(dw[j], xp[v], dacc[j][v]);
                }
            }
        }
    }

    // interpolation gather (K3 only)
    int   j0 = 0, j1 = 0, j2 = 0;
    float w0 = 0.f, w1 = 0.f, w2 = 0.f;
    if (GATHER) {
        j0 = g_kidx[ptc * 3 + 0];
        j1 = g_kidx[ptc * 3 + 1];
        j2 = g_kidx[ptc * 3 + 2];
        w0 = g_kw[ptc * 3 + 0];
        w1 = g_kw[ptc * 3 + 1];
        w2 = g_kw[ptc * 3 + 2];
    }

    if (!valid) return;

    float* dst = GATHER ? out : g_y2;
#pragma unroll
    for (int j = 0; j < 4; j++) {
        const float2 pv[3] = {unpack2(pacc[j][0]), unpack2(pacc[j][1]), unpack2(pacc[j][2])};
        const float2 dv[3] = {unpack2(dacc[j][0]), unpack2(dacc[j][1]), unpack2(dacc[j][2])};
#pragma unroll
        for (int h = 0; h < 2; h++) {
            const int o = og * 8 + 2 * j + h;
            const float p0 = h ? pv[0].y : pv[0].x;
            const float p1 = h ? pv[1].y : pv[1].x;
            const float p2 = h ? pv[2].y : pv[2].x;
            const float d0 = h ? dv[0].y : dv[0].x;
            const float d1 = h ? dv[1].y : dv[1].x;
            const float d2 = h ? dv[2].y : dv[2].x;
            const float dot = p0 * d0 + p1 * d1 + p2 * d2;
            const float dd  = d0 * d0 + d1 * d1 + d2 * d2;
            // out = p - (dot<0 ? 0.8*dot/(dd+eps) : 0) * d
            const float c = (dot >= 0.f) ? 0.f : (0.8f * dot / (dd + 1e-6f));
            float r0 = p0 - c * d0;
            float r1 = p1 - c * d1;
            float r2 = p2 - c * d2;
            if (GATHER) {
                const int b0i = (o * 3 + 0) * N2;
                const int b1i = (o * 3 + 1) * N2;
                const int b2i = (o * 3 + 2) * N2;
                r0 += w0 * __ldg(&g_y2[b0i + j0]) + w1 * __ldg(&g_y2[b0i + j1]) + w2 * __ldg(&g_y2[b0i + j2]);
                r1 += w0 * __ldg(&g_y2[b1i + j0]) + w1 * __ldg(&g_y2[b1i + j1]) + w2 * __ldg(&g_y2[b1i + j2]);
                r2 += w0 * __ldg(&g_y2[b2i + j0]) + w1 * __ldg(&g_y2[b2i + j1]) + w2 * __ldg(&g_y2[b2i + j2]);
            }
            dst[(o * 3 + 0) * N + pt] = r0;
            dst[(o * 3 + 1) * N + pt] = r1;
            dst[(o * 3 + 2) * N + pt] = r2;
        }
    }
}

// ---------------------------------------------------------------------------
// Exact k=3 NN per batch segment, brute force over staged smem chunks.
// Ranking uses r = |s|^2 - 2 q.s (monotone in d^2); final weights recompute
// the EXACT (q-s)^2 for the 3 winners to avoid cancellation error.
// ---------------------------------------------------------------------------
__global__ void __launch_bounds__(KNN_T) knn_kernel(
    const float* __restrict__ p1,   // [b*n1][3]
    const float* __restrict__ p2,   // [b*n2][3]
    int n1, int n2)
{
    __shared__ float4 sc[NCH];
    const int bI = blockIdx.y;
    const int fi = blockIdx.x * KNN_T + threadIdx.x;
    const int fic = (fi < n1) ? fi : (n1 - 1);
    const int gq = bI * n1 + fic;

    const float qx = p1[gq * 3 + 0];
    const float qy = p1[gq * 3 + 1];
    const float qz = p1[gq * 3 + 2];
    const float qa = -2.f * qx, qb = -2.f * qy, qc = -2.f * qz;

    float b0 = 3.4e38f, b1 = 3.4e38f, b2 = 3.4e38f;
    int   i0 = 0, i1 = 0, i2 = 0;

    for (int c0 = 0; c0 < n2; c0 += NCH) {
        const int cnt = min(NCH, n2 - c0);
        __syncthreads();
        for (int i = threadIdx.x; i < cnt; i += KNN_T) {
            const int gs = bI * n2 + c0 + i;
            const float sx = p2[gs * 3 + 0];
            const float sy = p2[gs * 3 + 1];
            const float sz = p2[gs * 3 + 2];
            sc[i] = make_float4(sx, sy, sz, sx * sx + sy * sy + sz * sz);
        }
        __syncthreads();

#pragma unroll 4
        for (int j = 0; j < cnt; j++) {
            const float4 s = sc[j];   // broadcast LDS.128
            const float r = fmaf(qa, s.x, fmaf(qb, s.y, fmaf(qc, s.z, s.w)));
            if (r < b2) {             // rarely taken warp-wide after warmup
                const int jj = c0 + j;
                if (r < b1) {
                    b2 = b1; i2 = i1;
                    if (r < b0) { b1 = b0; i1 = i0; b0 = r; i0 = jj; }
                    else        { b1 = r;  i1 = jj; }
                } else { b2 = r; i2 = jj; }
            }
        }
    }

    if (fi >= n1) return;

    // exact squared distances for the winners (matches reference arithmetic)
    const int s0 = bI * n2 + i0, s1 = bI * n2 + i1, s2 = bI * n2 + i2;
    float dx, dy, dz;
    dx = qx - p2[s0 * 3 + 0]; dy = qy - p2[s0 * 3 + 1]; dz = qz - p2[s0 * 3 + 2];
    const float d0 = dx * dx + dy * dy + dz * dz;
    dx = qx - p2[s1 * 3 + 0]; dy = qy - p2[s1 * 3 + 1]; dz = qz - p2[s1 * 3 + 2];
    const float d1 = dx * dx + dy * dy + dz * dz;
    dx = qx - p2[s2 * 3 + 0]; dy = qy - p2[s2 * 3 + 1]; dz = qz - p2[s2 * 3 + 2];
    const float d2 = dx * dx + dy * dy + dz * dz;

    const float w0 = 1.f / (d0 + 1e-8f);
    const float w1 = 1.f / (d1 + 1e-8f);
    const float w2 = 1.f / (d2 + 1e-8f);
    const float inv = 1.f / (w0 + w1 + w2);

    const int fo = (bI * n1 + fi) * 3;
    g_kidx[fo + 0] = s0;
    g_kidx[fo + 1] = s1;
    g_kidx[fo + 2] = s2;
    g_kw[fo + 0] = w0 * inv;
    g_kw[fo + 1] = w1 * inv;
    g_kw[fo + 2] = w2 * inv;
}

// ---------------------------------------------------------------------------
// Inputs (metadata order): p1, x1, o1, p2, x2, o2, w1_feat, w1_dir, w2_feat, w2_dir
// ---------------------------------------------------------------------------
extern "C" void kernel_launch(void* const* d_in, const int* in_sizes, int n_in,
                              void* d_out, int out_size)
{
    const float* p1  = (const float*)d_in[0];
    const float* x1  = (const float*)d_in[1];
    const float* p2  = (const float*)d_in[3];
    const float* x2  = (const float*)d_in[4];
    const float* w1f = (const float*)d_in[6];
    const float* w1d = (const float*)d_in[7];
    const float* w2f = (const float*)d_in[8];
    const float* w2d = (const float*)d_in[9];
    float* out = (float*)d_out;

    const int b    = in_sizes[2];              // 4
    const int N1   = in_sizes[0] / 3;          // 65536
    const int N2   = in_sizes[3] / 3;          // 16384
    const int Cin1 = in_sizes[1] / (3 * N1);   // 64
    const int Cin2 = in_sizes[4] / (3 * N2);   // 128
    const int n1   = N1 / b;
    const int n2   = N2 / b;

    // K1: y2 = VN(x2)  ->  g_y2
    vn_kernel<false><<<(N2 + PTS - 1) / PTS, 256>>>(x2, w2f, w2d, nullptr, Cin2, N2, 0);

    // K2: exact k=3 NN per batch  ->  g_kidx / g_kw
    dim3 kg((n1 + KNN_T - 1) / KNN_T, b);
    knn_kernel<<<kg, KNN_T>>>(p1, p2, n1, n2);

    // K3: out = VN(x1) + interp(g_y2)
    vn_kernel<true><<<(N1 + PTS - 1) / PTS, 256>>>(x1, w1f, w1d, out, Cin1, N1, N2);
}